// round 2
// baseline (speedup 1.0000x reference)
#include <cuda_runtime.h>
#include <cstdint>
#include <cstddef>

// Problem constants
#define B_   32
#define L_   512
#define H_   8
#define DH   64
#define DIN  512
#define HB   (H_ * B_)          // 256
#define NEGV (-4294967295.0f)   // -2^32 + 1

// ---------------------------------------------------------------------------
// Scratch (static device globals; no runtime allocation). 100 MB total.
// ---------------------------------------------------------------------------
__device__ float g_Q[(size_t)HB * L_ * DH];   // head-split Q  [hb][l][d]
__device__ float g_K[(size_t)HB * L_ * DH];   // head-split K
__device__ float g_V[(size_t)HB * L_ * DH];   // head-split V
__device__ float g_km[B_ * L_];               // key padding mask (0/1)
__device__ float g_qm[B_ * L_];               // query padding mask (0/1)

// ---------------------------------------------------------------------------
// Helpers
// ---------------------------------------------------------------------------
__device__ __forceinline__ float f2tf_f(float x) {
    uint32_t u;
    asm("cvt.rna.tf32.f32 %0, %1;" : "=r"(u) : "f"(x));
    return __uint_as_float(u);
}
__device__ __forceinline__ uint32_t f2tf_u(float x) {
    uint32_t u;
    asm("cvt.rna.tf32.f32 %0, %1;" : "=r"(u) : "f"(x));
    return u;
}

__device__ __forceinline__ void mma_tf32(float c[4],
                                         uint32_t a0, uint32_t a1, uint32_t a2, uint32_t a3,
                                         uint32_t b0, uint32_t b1) {
    asm volatile(
        "mma.sync.aligned.m16n8k8.row.col.f32.tf32.tf32.f32 "
        "{%0,%1,%2,%3}, {%4,%5,%6,%7}, {%8,%9}, {%0,%1,%2,%3};\n"
        : "+f"(c[0]), "+f"(c[1]), "+f"(c[2]), "+f"(c[3])
        : "r"(a0), "r"(a1), "r"(a2), "r"(a3), "r"(b0), "r"(b1));
}

// ---------------------------------------------------------------------------
// Kernel 1: padding masks. One warp per row (32768 warps).
// ---------------------------------------------------------------------------
__global__ __launch_bounds__(256) void mask_kernel(const float* __restrict__ query,
                                                   const float* __restrict__ key) {
    int t    = blockIdx.x * blockDim.x + threadIdx.x;
    int warp = t >> 5;
    int lane = t & 31;
    int which = warp >> 14;           // 0 = query, 1 = key
    int row   = warp & 16383;         // b*512 + l
    const float4* src = (const float4*)((which ? key : query) + (size_t)row * DIN);
    float s = 0.f;
#pragma unroll
    for (int i = 0; i < 4; i++) {
        float4 v = src[lane + 32 * i];
        s += (v.x + v.y) + (v.z + v.w);
    }
#pragma unroll
    for (int o = 16; o; o >>= 1) s += __shfl_xor_sync(0xffffffffu, s, o);
    if (lane == 0) (which ? g_km : g_qm)[row] = (s != 0.f) ? 1.f : 0.f;
}

// ---------------------------------------------------------------------------
// Kernel 2: projections. C[16384,512] = A[16384,512] @ W[512,512], tf32 mma.
// z = 0/1/2 -> (query,Wq)->g_Q, (key,Wk)->g_K, (key,Wv)->g_V, head-split out.
// CTA tile 128x128, K-step 32, 8 warps (4x2), warp tile 32x64.
// ---------------------------------------------------------------------------
__global__ __launch_bounds__(256) void proj_kernel(const float* __restrict__ query,
                                                   const float* __restrict__ key,
                                                   const float* __restrict__ Wq,
                                                   const float* __restrict__ Wk,
                                                   const float* __restrict__ Wv) {
    const int z = blockIdx.z;
    const float* A = (z == 0) ? query : key;
    const float* W = (z == 0) ? Wq : (z == 1) ? Wk : Wv;
    float* Dst = (z == 0) ? g_Q : (z == 1) ? g_K : g_V;

    const int m0 = blockIdx.y * 128;
    const int n0 = blockIdx.x * 128;

    __shared__ float As[128][36];
    __shared__ float Bs[32][132];

    const int tid  = threadIdx.x;
    const int lane = tid & 31;
    const int wid  = tid >> 5;
    const int wm   = wid & 3;
    const int wn   = wid >> 2;
    const int gid  = lane >> 2;
    const int tig  = lane & 3;

    float acc[2][8][4];
#pragma unroll
    for (int i = 0; i < 2; i++)
#pragma unroll
        for (int j = 0; j < 8; j++)
#pragma unroll
            for (int r = 0; r < 4; r++) acc[i][j][r] = 0.f;

    for (int k0 = 0; k0 < DIN; k0 += 32) {
        __syncthreads();
#pragma unroll
        for (int r = 0; r < 4; r++) {
            int e = tid + r * 256;
            int row = e >> 3, c4 = e & 7;
            float4 v = *(const float4*)(A + (size_t)(m0 + row) * DIN + k0 + c4 * 4);
            As[row][c4 * 4 + 0] = f2tf_f(v.x);
            As[row][c4 * 4 + 1] = f2tf_f(v.y);
            As[row][c4 * 4 + 2] = f2tf_f(v.z);
            As[row][c4 * 4 + 3] = f2tf_f(v.w);
        }
#pragma unroll
        for (int r = 0; r < 4; r++) {
            int e = tid + r * 256;
            int row = e >> 5, c4 = e & 31;
            float4 v = *(const float4*)(W + (size_t)(k0 + row) * 512 + n0 + c4 * 4);
            Bs[row][c4 * 4 + 0] = f2tf_f(v.x);
            Bs[row][c4 * 4 + 1] = f2tf_f(v.y);
            Bs[row][c4 * 4 + 2] = f2tf_f(v.z);
            Bs[row][c4 * 4 + 3] = f2tf_f(v.w);
        }
        __syncthreads();

#pragma unroll
        for (int kk = 0; kk < 32; kk += 8) {
            uint32_t a[2][4], b[8][2];
#pragma unroll
            for (int mi = 0; mi < 2; mi++) {
                int r = wm * 32 + mi * 16 + gid;
                a[mi][0] = __float_as_uint(As[r][kk + tig]);
                a[mi][1] = __float_as_uint(As[r + 8][kk + tig]);
                a[mi][2] = __float_as_uint(As[r][kk + 4 + tig]);
                a[mi][3] = __float_as_uint(As[r + 8][kk + 4 + tig]);
            }
#pragma unroll
            for (int ni = 0; ni < 8; ni++) {
                int c = wn * 64 + ni * 8 + gid;
                b[ni][0] = __float_as_uint(Bs[kk + tig][c]);
                b[ni][1] = __float_as_uint(Bs[kk + 4 + tig][c]);
            }
#pragma unroll
            for (int mi = 0; mi < 2; mi++)
#pragma unroll
                for (int ni = 0; ni < 8; ni++)
                    mma_tf32(acc[mi][ni], a[mi][0], a[mi][1], a[mi][2], a[mi][3],
                             b[ni][0], b[ni][1]);
        }
    }

#pragma unroll
    for (int mi = 0; mi < 2; mi++) {
#pragma unroll
        for (int ni = 0; ni < 8; ni++) {
            int gm = m0 + wm * 32 + mi * 16 + gid;
            int gn = n0 + wn * 64 + ni * 8 + tig * 2;
#pragma unroll
            for (int rr = 0; rr < 2; rr++) {
                int row = gm + rr * 8;
                int bb = row >> 9, ll = row & 511;
#pragma unroll
                for (int cc = 0; cc < 2; cc++) {
                    int col = gn + cc;
                    int h = col >> 6, d = col & 63;
                    Dst[((((size_t)h << 5) + bb) * 512 + ll) * 64 + d] = acc[mi][ni][rr * 2 + cc];
                }
            }
        }
    }
}

// ---------------------------------------------------------------------------
// Kernel 3: fused flash attention.
// Grid: (4 q-tiles, 256 hb). 256 threads = 8 warps; warp owns 16 q-rows.
// Br=128, Bc=64. Causal k-tile skip: only k-tiles 0..(2*qt+1) processed.
// P never hits memory: C-frag -> A-frag conversion via quad shuffles.
// ---------------------------------------------------------------------------
__global__ __launch_bounds__(256, 1) void attn_kernel(const float* __restrict__ query,
                                                      float* __restrict__ out) {
    const int hb = blockIdx.y;
    const int h  = hb >> 5;
    const int b  = hb & 31;
    const int m0 = blockIdx.x * 128;

    const float* Qh = g_Q + (size_t)hb * L_ * DH;
    const float* Kh = g_K + (size_t)hb * L_ * DH;
    const float* Vh = g_V + (size_t)hb * L_ * DH;

    __shared__ float sm[128 * 68];     // 34.8 KB: Q staging, then {K^T | V} tiles

    const int tid  = threadIdx.x;
    const int lane = tid & 31;
    const int wid  = tid >> 5;
    const int gid  = lane >> 2;
    const int tig  = lane & 3;
    const int r0   = wid * 16 + gid;
    const int r1   = r0 + 8;
    const int q0   = m0 + r0;
    const int q1   = m0 + r1;

    // ---- stage Q tile (128x64, tf32) and load fragments (held all kernel) ----
#pragma unroll
    for (int r = 0; r < 8; r++) {
        int e = tid + r * 256;
        int row = e >> 4, c4 = e & 15;
        float4 v = *(const float4*)(Qh + (size_t)(m0 + row) * DH + c4 * 4);
        v.x = f2tf_f(v.x); v.y = f2tf_f(v.y); v.z = f2tf_f(v.z); v.w = f2tf_f(v.w);
        *(float4*)&sm[row * 68 + c4 * 4] = v;
    }
    __syncthreads();
    uint32_t Qa[8][4];
#pragma unroll
    for (int kg = 0; kg < 8; kg++) {
        Qa[kg][0] = __float_as_uint(sm[r0 * 68 + kg * 8 + tig]);
        Qa[kg][1] = __float_as_uint(sm[r1 * 68 + kg * 8 + tig]);
        Qa[kg][2] = __float_as_uint(sm[r0 * 68 + kg * 8 + 4 + tig]);
        Qa[kg][3] = __float_as_uint(sm[r1 * 68 + kg * 8 + 4 + tig]);
    }
    __syncthreads();

    float o[8][4];
#pragma unroll
    for (int di = 0; di < 8; di++)
#pragma unroll
        for (int j = 0; j < 4; j++) o[di][j] = 0.f;
    float mrun0 = -3.4e38f, mrun1 = -3.4e38f;
    float lrun0 = 0.f, lrun1 = 0.f;

    const int nkt = (m0 >> 6) + 2;   // causal: k0 <= m0+64
    for (int kt = 0; kt < nkt; kt++) {
        const int k0 = kt * 64;

        // ---- stage K^T (d-major) and V (k-major) tiles ----
#pragma unroll
        for (int r = 0; r < 4; r++) {
            int e = tid + r * 256;
            int kc = e >> 4, d4 = e & 15;
            float4 v = *(const float4*)(Kh + (size_t)(k0 + kc) * DH + d4 * 4);
            sm[(d4 * 4 + 0) * 68 + kc] = f2tf_f(v.x);
            sm[(d4 * 4 + 1) * 68 + kc] = f2tf_f(v.y);
            sm[(d4 * 4 + 2) * 68 + kc] = f2tf_f(v.z);
            sm[(d4 * 4 + 3) * 68 + kc] = f2tf_f(v.w);
        }
#pragma unroll
        for (int r = 0; r < 4; r++) {
            int e = tid + r * 256;
            int kc = e >> 4, d4 = e & 15;
            float4 v = *(const float4*)(Vh + (size_t)(k0 + kc) * DH + d4 * 4);
            v.x = f2tf_f(v.x); v.y = f2tf_f(v.y); v.z = f2tf_f(v.z); v.w = f2tf_f(v.w);
            *(float4*)&sm[64 * 68 + kc * 68 + d4 * 4] = v;
        }
        __syncthreads();

        // ---- S = Q @ K^T ----
        float s[8][4];
#pragma unroll
        for (int ni = 0; ni < 8; ni++)
#pragma unroll
            for (int j = 0; j < 4; j++) s[ni][j] = 0.f;
#pragma unroll
        for (int kg = 0; kg < 8; kg++) {
#pragma unroll
            for (int ni = 0; ni < 8; ni++) {
                uint32_t b0 = __float_as_uint(sm[(kg * 8 + tig) * 68 + ni * 8 + gid]);
                uint32_t b1 = __float_as_uint(sm[(kg * 8 + 4 + tig) * 68 + ni * 8 + gid]);
                mma_tf32(s[ni], Qa[kg][0], Qa[kg][1], Qa[kg][2], Qa[kg][3], b0, b1);
            }
        }

        // ---- scale + causal + key-mask ----
#pragma unroll
        for (int ni = 0; ni < 8; ni++) {
            int c0 = k0 + ni * 8 + tig * 2;
            float km0 = g_km[b * 512 + c0];
            float km1 = g_km[b * 512 + c0 + 1];
            s[ni][0] = (c0 > q0     || km0 == 0.f) ? NEGV : s[ni][0] * 0.125f;
            s[ni][1] = (c0 + 1 > q0 || km1 == 0.f) ? NEGV : s[ni][1] * 0.125f;
            s[ni][2] = (c0 > q1     || km0 == 0.f) ? NEGV : s[ni][2] * 0.125f;
            s[ni][3] = (c0 + 1 > q1 || km1 == 0.f) ? NEGV : s[ni][3] * 0.125f;
        }

        // ---- online softmax ----
        float mx0 = -3.4e38f, mx1 = -3.4e38f;
#pragma unroll
        for (int ni = 0; ni < 8; ni++) {
            mx0 = fmaxf(mx0, fmaxf(s[ni][0], s[ni][1]));
            mx1 = fmaxf(mx1, fmaxf(s[ni][2], s[ni][3]));
        }
        mx0 = fmaxf(mx0, __shfl_xor_sync(0xffffffffu, mx0, 1));
        mx0 = fmaxf(mx0, __shfl_xor_sync(0xffffffffu, mx0, 2));
        mx1 = fmaxf(mx1, __shfl_xor_sync(0xffffffffu, mx1, 1));
        mx1 = fmaxf(mx1, __shfl_xor_sync(0xffffffffu, mx1, 2));

        float mn0 = fmaxf(mrun0, mx0), mn1 = fmaxf(mrun1, mx1);
        float al0 = __expf(mrun0 - mn0), al1 = __expf(mrun1 - mn1);
        mrun0 = mn0; mrun1 = mn1;

        float p[8][4];
        float rs0 = 0.f, rs1 = 0.f;
#pragma unroll
        for (int ni = 0; ni < 8; ni++) {
            p[ni][0] = __expf(s[ni][0] - mn0);
            p[ni][1] = __expf(s[ni][1] - mn0);
            p[ni][2] = __expf(s[ni][2] - mn1);
            p[ni][3] = __expf(s[ni][3] - mn1);
            rs0 += p[ni][0] + p[ni][1];
            rs1 += p[ni][2] + p[ni][3];
        }
        rs0 += __shfl_xor_sync(0xffffffffu, rs0, 1);
        rs0 += __shfl_xor_sync(0xffffffffu, rs0, 2);
        rs1 += __shfl_xor_sync(0xffffffffu, rs1, 1);
        rs1 += __shfl_xor_sync(0xffffffffu, rs1, 2);
        lrun0 = lrun0 * al0 + rs0;
        lrun1 = lrun1 * al1 + rs1;
#pragma unroll
        for (int di = 0; di < 8; di++) {
            o[di][0] *= al0; o[di][1] *= al0;
            o[di][2] *= al1; o[di][3] *= al1;
        }

        // ---- O += P @ V  (C-frag -> A-frag via quad shuffles) ----
        const int srcA = (lane & ~3) | (tig >> 1);
        const int srcB = srcA + 2;
        const bool sel = (tig & 1);
#pragma unroll
        for (int kg = 0; kg < 8; kg++) {
            uint32_t pc0 = f2tf_u(p[kg][0]);
            uint32_t pc1 = f2tf_u(p[kg][1]);
            uint32_t pc2 = f2tf_u(p[kg][2]);
            uint32_t pc3 = f2tf_u(p[kg][3]);
            uint32_t uA0 = __shfl_sync(0xffffffffu, pc0, srcA);
            uint32_t uA1 = __shfl_sync(0xffffffffu, pc1, srcA);
            uint32_t uA2 = __shfl_sync(0xffffffffu, pc2, srcA);
            uint32_t uA3 = __shfl_sync(0xffffffffu, pc3, srcA);
            uint32_t uB0 = __shfl_sync(0xffffffffu, pc0, srcB);
            uint32_t uB1 = __shfl_sync(0xffffffffu, pc1, srcB);
            uint32_t uB2 = __shfl_sync(0xffffffffu, pc2, srcB);
            uint32_t uB3 = __shfl_sync(0xffffffffu, pc3, srcB);
            uint32_t a0 = sel ? uA1 : uA0;   // (r0, kg*8+tig)
            uint32_t a1 = sel ? uA3 : uA2;   // (r1, kg*8+tig)
            uint32_t a2 = sel ? uB1 : uB0;   // (r0, kg*8+tig+4)
            uint32_t a3 = sel ? uB3 : uB2;   // (r1, kg*8+tig+4)
#pragma unroll
            for (int di = 0; di < 8; di++) {
                uint32_t b0 = __float_as_uint(sm[64 * 68 + (kg * 8 + tig) * 68 + di * 8 + gid]);
                uint32_t b1 = __float_as_uint(sm[64 * 68 + (kg * 8 + 4 + tig) * 68 + di * 8 + gid]);
                mma_tf32(o[di], a0, a1, a2, a3, b0, b1);
            }
        }
        __syncthreads();
    }

    // ---- epilogue: normalize, qmask, +query, merged-head store ----
    float sc0 = g_qm[b * 512 + q0] / lrun0;
    float sc1 = g_qm[b * 512 + q1] / lrun1;
#pragma unroll
    for (int di = 0; di < 8; di++) {
        int col = h * 64 + di * 8 + tig * 2;
        size_t i0 = ((size_t)(b * 512 + q0)) * 512 + col;
        size_t i1 = ((size_t)(b * 512 + q1)) * 512 + col;
        float2 qv0 = *(const float2*)(query + i0);
        float2 qv1 = *(const float2*)(query + i1);
        float2 w0, w1;
        w0.x = o[di][0] * sc0 + qv0.x;
        w0.y = o[di][1] * sc0 + qv0.y;
        w1.x = o[di][2] * sc1 + qv1.x;
        w1.y = o[di][3] * sc1 + qv1.y;
        *(float2*)(out + i0) = w0;
        *(float2*)(out + i1) = w1;
    }
}

// ---------------------------------------------------------------------------
// Launch
// ---------------------------------------------------------------------------
extern "C" void kernel_launch(void* const* d_in, const int* in_sizes, int n_in,
                              void* d_out, int out_size) {
    const float* query = (const float*)d_in[0];
    const float* key   = (const float*)d_in[1];
    const float* Wq    = (const float*)d_in[2];
    const float* Wk    = (const float*)d_in[3];
    const float* Wv    = (const float*)d_in[4];
    float* out = (float*)d_out;

    mask_kernel<<<4096, 256>>>(query, key);
    proj_kernel<<<dim3(4, 128, 3), 256>>>(query, key, Wq, Wk, Wv);
    attn_kernel<<<dim3(4, HB), 256>>>(query, out);
}

// round 3
// speedup vs baseline: 2.1958x; 2.1958x over previous
#include <cuda_runtime.h>
#include <cuda_fp16.h>
#include <cstdint>
#include <cstddef>

// Problem constants
#define B_   32
#define L_   512
#define H_   8
#define DH   64
#define DIN  512
#define HB   (H_ * B_)          // 256
#define NEGV (-4294967295.0f)   // -2^32 + 1

// ---------------------------------------------------------------------------
// Scratch (static device globals)
// ---------------------------------------------------------------------------
__device__ __half g_Ah[(size_t)2 * 16384 * 512];   // fp16 copies of query,key
__device__ __half g_Wt[(size_t)3 * 512 * 512];     // W^T (n-major, k contiguous) fp16
__device__ __half g_Qh[(size_t)HB * L_ * DH];      // head-split Q  [hb][l][d]
__device__ __half g_Kh[(size_t)HB * L_ * DH];      // head-split K  [hb][l][d]
__device__ __half g_Vt[(size_t)HB * DH * L_];      // head-split V transposed [hb][d][l]
__device__ float  g_km[B_ * L_];                   // key padding mask (0/1)
__device__ float  g_qm[B_ * L_];                   // query padding mask (0/1)

// ---------------------------------------------------------------------------
// fp16 mma m16n8k16, fp32 accumulate
// ---------------------------------------------------------------------------
__device__ __forceinline__ void mma_f16(float c[4],
                                        uint32_t a0, uint32_t a1, uint32_t a2, uint32_t a3,
                                        uint32_t b0, uint32_t b1) {
    asm volatile(
        "mma.sync.aligned.m16n8k16.row.col.f32.f16.f16.f32 "
        "{%0,%1,%2,%3}, {%4,%5,%6,%7}, {%8,%9}, {%0,%1,%2,%3};\n"
        : "+f"(c[0]), "+f"(c[1]), "+f"(c[2]), "+f"(c[3])
        : "r"(a0), "r"(a1), "r"(a2), "r"(a3), "r"(b0), "r"(b1));
}

__device__ __forceinline__ uint32_t h2u(float lo, float hi) {
    __half2 h = __floats2half2_rn(lo, hi);
    return *(uint32_t*)&h;
}

// ---------------------------------------------------------------------------
// Kernel 1: padding masks + fp32 -> fp16 conversion of query/key.
// One warp per row; 32768 warps.
// ---------------------------------------------------------------------------
__global__ __launch_bounds__(256) void prep_qk_kernel(const float* __restrict__ query,
                                                      const float* __restrict__ key) {
    int t    = blockIdx.x * blockDim.x + threadIdx.x;
    int warp = t >> 5;
    int lane = t & 31;
    int which = warp >> 14;           // 0 = query, 1 = key
    int row   = warp & 16383;         // b*512 + l
    const float4* src = (const float4*)((which ? key : query) + (size_t)row * DIN);
    __half* dst = g_Ah + ((size_t)which * 16384 + row) * 512;
    float s = 0.f;
#pragma unroll
    for (int i = 0; i < 4; i++) {
        float4 v = src[lane + 32 * i];
        s += (v.x + v.y) + (v.z + v.w);
        __half2 h0 = __floats2half2_rn(v.x, v.y);
        __half2 h1 = __floats2half2_rn(v.z, v.w);
        uint2 u = make_uint2(*(uint32_t*)&h0, *(uint32_t*)&h1);
        *(uint2*)(dst + (size_t)(lane + 32 * i) * 4) = u;
    }
#pragma unroll
    for (int o = 16; o; o >>= 1) s += __shfl_xor_sync(0xffffffffu, s, o);
    if (lane == 0) (which ? g_km : g_qm)[row] = (s != 0.f) ? 1.f : 0.f;
}

// ---------------------------------------------------------------------------
// Kernel 2: W transpose + convert.  g_Wt[z][n][k] = half(W_z[k][n]).
// Grid (16,16,3), 256 threads, 32x32 tiles.
// ---------------------------------------------------------------------------
__global__ __launch_bounds__(256) void prep_w_kernel(const float* __restrict__ Wq,
                                                     const float* __restrict__ Wk,
                                                     const float* __restrict__ Wv) {
    const int z  = blockIdx.z;
    const float* W = (z == 0) ? Wq : (z == 1) ? Wk : Wv;
    const int k0 = blockIdx.x * 32;
    const int n0 = blockIdx.y * 32;
    __shared__ float ts[32][33];
    int e = threadIdx.x;
    {
        int kr = e >> 3, c4 = e & 7;
        float4 v = *(const float4*)(W + (size_t)(k0 + kr) * 512 + n0 + c4 * 4);
        ts[kr][c4 * 4 + 0] = v.x;
        ts[kr][c4 * 4 + 1] = v.y;
        ts[kr][c4 * 4 + 2] = v.z;
        ts[kr][c4 * 4 + 3] = v.w;
    }
    __syncthreads();
    {
        int n = e >> 3, g = e & 7;
        __half2 h0 = __floats2half2_rn(ts[g * 4 + 0][n], ts[g * 4 + 1][n]);
        __half2 h1 = __floats2half2_rn(ts[g * 4 + 2][n], ts[g * 4 + 3][n]);
        uint2 u = make_uint2(*(uint32_t*)&h0, *(uint32_t*)&h1);
        *(uint2*)(g_Wt + ((size_t)z * 512 + n0 + n) * 512 + k0 + g * 4) = u;
    }
}

// ---------------------------------------------------------------------------
// Kernel 3: projections, fp16 mma m16n8k16.
// C[16384,512] = A[16384,512] @ W[512,512].
// z = 0/1/2 -> (q,Wq)->g_Qh, (k,Wk)->g_Kh, (k,Wv)->g_Vt (transposed).
// CTA tile 128x128, K-step 32, 8 warps (4x2), warp tile 32x64.
// ---------------------------------------------------------------------------
__global__ __launch_bounds__(256, 2) void proj_kernel() {
    const int z = blockIdx.z;
    const __half* A  = g_Ah + (size_t)(z ? 1 : 0) * 16384 * 512;
    const __half* Wt = g_Wt + (size_t)z * 512 * 512;

    const int m0 = blockIdx.y * 128;
    const int n0 = blockIdx.x * 128;

    __shared__ __align__(16) __half As[128 * 40];   // rows padded to 40 halfs
    __shared__ __align__(16) __half Bs[128 * 40];   // Bs[n][k], k contiguous

    const int tid  = threadIdx.x;
    const int lane = tid & 31;
    const int wid  = tid >> 5;
    const int wm   = wid & 3;
    const int wn   = wid >> 2;
    const int gid  = lane >> 2;
    const int tig  = lane & 3;

    float acc[2][8][4];
#pragma unroll
    for (int i = 0; i < 2; i++)
#pragma unroll
        for (int j = 0; j < 8; j++)
#pragma unroll
            for (int r = 0; r < 4; r++) acc[i][j][r] = 0.f;

    for (int k0 = 0; k0 < DIN; k0 += 32) {
        __syncthreads();
        // stage A tile 128x32 halfs: 512 uint4, 2 per thread
#pragma unroll
        for (int r = 0; r < 2; r++) {
            int e = tid + r * 256;
            int row = e >> 2, c8 = e & 3;
            uint4 v = *(const uint4*)(A + (size_t)(m0 + row) * 512 + k0 + c8 * 8);
            *(uint4*)(As + row * 40 + c8 * 8) = v;
        }
        // stage B tile [n 128][k 32] halfs
#pragma unroll
        for (int r = 0; r < 2; r++) {
            int e = tid + r * 256;
            int n = e >> 2, c8 = e & 3;
            uint4 v = *(const uint4*)(Wt + (size_t)(n0 + n) * 512 + k0 + c8 * 8);
            *(uint4*)(Bs + n * 40 + c8 * 8) = v;
        }
        __syncthreads();

#pragma unroll
        for (int kg = 0; kg < 2; kg++) {
            uint32_t a[2][4];
#pragma unroll
            for (int mi = 0; mi < 2; mi++) {
                int r = wm * 32 + mi * 16 + gid;
                a[mi][0] = *(const uint32_t*)&As[r * 40 + kg * 16 + 2 * tig];
                a[mi][1] = *(const uint32_t*)&As[(r + 8) * 40 + kg * 16 + 2 * tig];
                a[mi][2] = *(const uint32_t*)&As[r * 40 + kg * 16 + 8 + 2 * tig];
                a[mi][3] = *(const uint32_t*)&As[(r + 8) * 40 + kg * 16 + 8 + 2 * tig];
            }
#pragma unroll
            for (int ni = 0; ni < 8; ni++) {
                int n = wn * 64 + ni * 8 + gid;
                uint32_t b0 = *(const uint32_t*)&Bs[n * 40 + kg * 16 + 2 * tig];
                uint32_t b1 = *(const uint32_t*)&Bs[n * 40 + kg * 16 + 8 + 2 * tig];
                mma_f16(acc[0][ni], a[0][0], a[0][1], a[0][2], a[0][3], b0, b1);
                mma_f16(acc[1][ni], a[1][0], a[1][1], a[1][2], a[1][3], b0, b1);
            }
        }
    }

    // epilogue
#pragma unroll
    for (int mi = 0; mi < 2; mi++) {
#pragma unroll
        for (int ni = 0; ni < 8; ni++) {
            int gm = m0 + wm * 32 + mi * 16 + gid;
            int gn = n0 + wn * 64 + ni * 8 + tig * 2;
            int h = gn >> 6, d = gn & 63;
#pragma unroll
            for (int rr = 0; rr < 2; rr++) {
                int row = gm + rr * 8;
                int bb = row >> 9, ll = row & 511;
                float c0 = acc[mi][ni][rr * 2 + 0];
                float c1 = acc[mi][ni][rr * 2 + 1];
                int hb = h * 32 + bb;
                if (z == 2) {
                    // V transposed: [hb][d][l]
                    size_t base = ((size_t)hb * 64 + d) * 512 + ll;
                    g_Vt[base]       = __float2half_rn(c0);
                    g_Vt[base + 512] = __float2half_rn(c1);
                } else {
                    __half2 hv = __floats2half2_rn(c0, c1);
                    __half* dst = (z == 0) ? g_Qh : g_Kh;
                    *(__half2*)(dst + ((size_t)hb * 512 + ll) * 64 + d) = hv;
                }
            }
        }
    }
}

// ---------------------------------------------------------------------------
// Kernel 4: fused flash attention, fp16 mma.
// Grid (4 q-tiles, 256 hb). 8 warps, warp owns 16 q-rows. Br=128, Bc=64.
// P->A fragment conversion is layout-exact (no shuffles).
// ---------------------------------------------------------------------------
__global__ __launch_bounds__(256, 2) void attn_kernel(const float* __restrict__ query,
                                                      float* __restrict__ out) {
    const int hb = blockIdx.y;
    const int h  = hb >> 5;
    const int b  = hb & 31;
    const int m0 = blockIdx.x * 128;

    const __half* Qh = g_Qh + (size_t)hb * L_ * DH;
    const __half* Kh = g_Kh + (size_t)hb * L_ * DH;
    const __half* Vt = g_Vt + (size_t)hb * DH * L_;

    // 9216 halfs = 18.4KB. Used first for Q staging (128x72), then Kt(64x72)+Vs(64x72).
    __shared__ __align__(16) __half sm[9216];
    __half* Kt = sm;            // [kcol][d]  d contiguous
    __half* Vs = sm + 64 * 72;  // [d][kcol]  kcol contiguous

    const int tid  = threadIdx.x;
    const int lane = tid & 31;
    const int wid  = tid >> 5;
    const int gid  = lane >> 2;
    const int tig  = lane & 3;
    const int r0   = wid * 16 + gid;
    const int r1   = r0 + 8;
    const int q0   = m0 + r0;
    const int q1   = m0 + r1;

    // ---- stage Q tile (128 rows x 64 halfs) and read fragments ----
#pragma unroll
    for (int r = 0; r < 4; r++) {
        int e = tid + r * 256;
        int row = e >> 3, c8 = e & 7;
        uint4 v = *(const uint4*)(Qh + (size_t)(m0 + row) * 64 + c8 * 8);
        *(uint4*)(sm + row * 72 + c8 * 8) = v;
    }
    __syncthreads();
    uint32_t Qa[4][4];
#pragma unroll
    for (int kg = 0; kg < 4; kg++) {
        Qa[kg][0] = *(const uint32_t*)&sm[r0 * 72 + kg * 16 + 2 * tig];
        Qa[kg][1] = *(const uint32_t*)&sm[r1 * 72 + kg * 16 + 2 * tig];
        Qa[kg][2] = *(const uint32_t*)&sm[r0 * 72 + kg * 16 + 8 + 2 * tig];
        Qa[kg][3] = *(const uint32_t*)&sm[r1 * 72 + kg * 16 + 8 + 2 * tig];
    }

    float o[8][4];
#pragma unroll
    for (int di = 0; di < 8; di++)
#pragma unroll
        for (int j = 0; j < 4; j++) o[di][j] = 0.f;
    float mrun0 = -3.4e38f, mrun1 = -3.4e38f;
    float lrun0 = 0.f, lrun1 = 0.f;

    const int nkt = (m0 >> 6) + 2;   // causal: process k-tiles with k0 <= m0+64
    for (int kt = 0; kt < nkt; kt++) {
        const int k0 = kt * 64;
        __syncthreads();   // protect previous tile (and initial Q frags)

        // stage K tile [kc][d] (straight copy) and V tile [d][kc] (straight copy
        // from pre-transposed g_Vt)
#pragma unroll
        for (int r = 0; r < 2; r++) {
            int e = tid + r * 256;
            int kc = e >> 3, c8 = e & 7;
            uint4 v = *(const uint4*)(Kh + (size_t)(k0 + kc) * 64 + c8 * 8);
            *(uint4*)(Kt + kc * 72 + c8 * 8) = v;
        }
#pragma unroll
        for (int r = 0; r < 2; r++) {
            int e = tid + r * 256;
            int d = e >> 3, c8 = e & 7;
            uint4 v = *(const uint4*)(Vt + (size_t)d * 512 + k0 + c8 * 8);
            *(uint4*)(Vs + d * 72 + c8 * 8) = v;
        }
        __syncthreads();

        // ---- S = Q @ K^T ----
        float s[8][4];
#pragma unroll
        for (int ni = 0; ni < 8; ni++)
#pragma unroll
            for (int j = 0; j < 4; j++) s[ni][j] = 0.f;
#pragma unroll
        for (int kg = 0; kg < 4; kg++) {
#pragma unroll
            for (int ni = 0; ni < 8; ni++) {
                const __half* kp = &Kt[(ni * 8 + gid) * 72 + kg * 16 + 2 * tig];
                uint32_t b0 = *(const uint32_t*)kp;
                uint32_t b1 = *(const uint32_t*)(kp + 8);
                mma_f16(s[ni], Qa[kg][0], Qa[kg][1], Qa[kg][2], Qa[kg][3], b0, b1);
            }
        }

        // ---- scale + causal + key-mask ----
#pragma unroll
        for (int ni = 0; ni < 8; ni++) {
            int c0 = k0 + ni * 8 + tig * 2;
            float km0 = g_km[b * 512 + c0];
            float km1 = g_km[b * 512 + c0 + 1];
            s[ni][0] = (c0 > q0     || km0 == 0.f) ? NEGV : s[ni][0] * 0.125f;
            s[ni][1] = (c0 + 1 > q0 || km1 == 0.f) ? NEGV : s[ni][1] * 0.125f;
            s[ni][2] = (c0 > q1     || km0 == 0.f) ? NEGV : s[ni][2] * 0.125f;
            s[ni][3] = (c0 + 1 > q1 || km1 == 0.f) ? NEGV : s[ni][3] * 0.125f;
        }

        // ---- online softmax ----
        float mx0 = -3.4e38f, mx1 = -3.4e38f;
#pragma unroll
        for (int ni = 0; ni < 8; ni++) {
            mx0 = fmaxf(mx0, fmaxf(s[ni][0], s[ni][1]));
            mx1 = fmaxf(mx1, fmaxf(s[ni][2], s[ni][3]));
        }
        mx0 = fmaxf(mx0, __shfl_xor_sync(0xffffffffu, mx0, 1));
        mx0 = fmaxf(mx0, __shfl_xor_sync(0xffffffffu, mx0, 2));
        mx1 = fmaxf(mx1, __shfl_xor_sync(0xffffffffu, mx1, 1));
        mx1 = fmaxf(mx1, __shfl_xor_sync(0xffffffffu, mx1, 2));

        float mn0 = fmaxf(mrun0, mx0), mn1 = fmaxf(mrun1, mx1);
        float al0 = __expf(mrun0 - mn0), al1 = __expf(mrun1 - mn1);
        mrun0 = mn0; mrun1 = mn1;

        float rs0 = 0.f, rs1 = 0.f;
#pragma unroll
        for (int ni = 0; ni < 8; ni++) {
            s[ni][0] = __expf(s[ni][0] - mn0);
            s[ni][1] = __expf(s[ni][1] - mn0);
            s[ni][2] = __expf(s[ni][2] - mn1);
            s[ni][3] = __expf(s[ni][3] - mn1);
            rs0 += s[ni][0] + s[ni][1];
            rs1 += s[ni][2] + s[ni][3];
        }
        rs0 += __shfl_xor_sync(0xffffffffu, rs0, 1);
        rs0 += __shfl_xor_sync(0xffffffffu, rs0, 2);
        rs1 += __shfl_xor_sync(0xffffffffu, rs1, 1);
        rs1 += __shfl_xor_sync(0xffffffffu, rs1, 2);
        lrun0 = lrun0 * al0 + rs0;
        lrun1 = lrun1 * al1 + rs1;
#pragma unroll
        for (int di = 0; di < 8; di++) {
            o[di][0] *= al0; o[di][1] *= al0;
            o[di][2] *= al1; o[di][3] *= al1;
        }

        // ---- O += P @ V : C-frag layout IS the fp16 A-frag layout ----
#pragma unroll
        for (int kg = 0; kg < 4; kg++) {
            uint32_t a0 = h2u(s[2 * kg][0],     s[2 * kg][1]);
            uint32_t a1 = h2u(s[2 * kg][2],     s[2 * kg][3]);
            uint32_t a2 = h2u(s[2 * kg + 1][0], s[2 * kg + 1][1]);
            uint32_t a3 = h2u(s[2 * kg + 1][2], s[2 * kg + 1][3]);
#pragma unroll
            for (int di = 0; di < 8; di++) {
                const __half* vp = &Vs[(di * 8 + gid) * 72 + kg * 16 + 2 * tig];
                uint32_t b0 = *(const uint32_t*)vp;
                uint32_t b1 = *(const uint32_t*)(vp + 8);
                mma_f16(o[di], a0, a1, a2, a3, b0, b1);
            }
        }
    }

    // ---- epilogue: normalize, qmask, +query, merged-head store ----
    float sc0 = g_qm[b * 512 + q0] / lrun0;
    float sc1 = g_qm[b * 512 + q1] / lrun1;
#pragma unroll
    for (int di = 0; di < 8; di++) {
        int col = h * 64 + di * 8 + tig * 2;
        size_t i0 = ((size_t)(b * 512 + q0)) * 512 + col;
        size_t i1 = ((size_t)(b * 512 + q1)) * 512 + col;
        float2 qv0 = *(const float2*)(query + i0);
        float2 qv1 = *(const float2*)(query + i1);
        float2 w0, w1;
        w0.x = o[di][0] * sc0 + qv0.x;
        w0.y = o[di][1] * sc0 + qv0.y;
        w1.x = o[di][2] * sc1 + qv1.x;
        w1.y = o[di][3] * sc1 + qv1.y;
        *(float2*)(out + i0) = w0;
        *(float2*)(out + i1) = w1;
    }
}

// ---------------------------------------------------------------------------
// Launch
// ---------------------------------------------------------------------------
extern "C" void kernel_launch(void* const* d_in, const int* in_sizes, int n_in,
                              void* d_out, int out_size) {
    const float* query = (const float*)d_in[0];
    const float* key   = (const float*)d_in[1];
    const float* Wq    = (const float*)d_in[2];
    const float* Wk    = (const float*)d_in[3];
    const float* Wv    = (const float*)d_in[4];
    float* out = (float*)d_out;

    prep_qk_kernel<<<4096, 256>>>(query, key);
    prep_w_kernel<<<dim3(16, 16, 3), 256>>>(Wq, Wk, Wv);
    proj_kernel<<<dim3(4, 128, 3), 256>>>();
    attn_kernel<<<dim3(4, HB), 256>>>(query, out);
}

// round 5
// speedup vs baseline: 2.7276x; 1.2422x over previous
#include <cuda_runtime.h>
#include <cuda_fp16.h>
#include <cstdint>
#include <cstddef>

// Problem constants
#define B_   32
#define L_   512
#define H_   8
#define DH   64
#define DIN  512
#define HB   (H_ * B_)          // 256
#define NEGV (-4294967295.0f)   // -2^32 + 1

// ---------------------------------------------------------------------------
// Scratch (static device globals)
// ---------------------------------------------------------------------------
__device__ __half g_Ah[(size_t)2 * 16384 * 512];   // fp16 copies of query,key
__device__ __half g_Wt[(size_t)3 * 512 * 512];     // W^T (n-major, k contiguous) fp16
__device__ __half g_Qh[(size_t)HB * L_ * DH];      // head-split Q  [hb][l][d]
__device__ __half g_Kh[(size_t)HB * L_ * DH];      // head-split K  [hb][l][d]
__device__ __half g_Vt[(size_t)HB * DH * L_];      // head-split V transposed [hb][d][l]
__device__ float  g_km[B_ * L_];                   // key padding mask (0/1)
__device__ float  g_qm[B_ * L_];                   // query padding mask (0/1)

// ---------------------------------------------------------------------------
// Helpers
// ---------------------------------------------------------------------------
__device__ __forceinline__ void mma_f16(float c[4],
                                        uint32_t a0, uint32_t a1, uint32_t a2, uint32_t a3,
                                        uint32_t b0, uint32_t b1) {
    asm volatile(
        "mma.sync.aligned.m16n8k16.row.col.f32.f16.f16.f32 "
        "{%0,%1,%2,%3}, {%4,%5,%6,%7}, {%8,%9}, {%0,%1,%2,%3};\n"
        : "+f"(c[0]), "+f"(c[1]), "+f"(c[2]), "+f"(c[3])
        : "r"(a0), "r"(a1), "r"(a2), "r"(a3), "r"(b0), "r"(b1));
}

__device__ __forceinline__ uint32_t h2u(float lo, float hi) {
    __half2 h = __floats2half2_rn(lo, hi);
    return *(uint32_t*)&h;
}

__device__ __forceinline__ void ldsm4(uint32_t& r0, uint32_t& r1, uint32_t& r2, uint32_t& r3,
                                      uint32_t addr) {
    asm volatile("ldmatrix.sync.aligned.m8n8.x4.shared.b16 {%0,%1,%2,%3}, [%4];"
                 : "=r"(r0), "=r"(r1), "=r"(r2), "=r"(r3) : "r"(addr));
}

__device__ __forceinline__ void cp16(uint32_t dst, const void* src) {
    asm volatile("cp.async.cg.shared.global [%0], [%1], 16;" :: "r"(dst), "l"(src));
}
#define CP_COMMIT() asm volatile("cp.async.commit_group;")
#define CP_WAIT0()  asm volatile("cp.async.wait_group 0;")
#define CP_WAIT1()  asm volatile("cp.async.wait_group 1;")

// ---------------------------------------------------------------------------
// Kernel 1: padding masks + fp32 -> fp16 conversion of query/key.
// ---------------------------------------------------------------------------
__global__ __launch_bounds__(256) void prep_qk_kernel(const float* __restrict__ query,
                                                      const float* __restrict__ key) {
    int t    = blockIdx.x * blockDim.x + threadIdx.x;
    int warp = t >> 5;
    int lane = t & 31;
    int which = warp >> 14;
    int row   = warp & 16383;
    const float4* src = (const float4*)((which ? key : query) + (size_t)row * DIN);
    __half* dst = g_Ah + ((size_t)which * 16384 + row) * 512;
    float s = 0.f;
#pragma unroll
    for (int i = 0; i < 4; i++) {
        float4 v = src[lane + 32 * i];
        s += (v.x + v.y) + (v.z + v.w);
        __half2 h0 = __floats2half2_rn(v.x, v.y);
        __half2 h1 = __floats2half2_rn(v.z, v.w);
        uint2 u = make_uint2(*(uint32_t*)&h0, *(uint32_t*)&h1);
        *(uint2*)(dst + (size_t)(lane + 32 * i) * 4) = u;
    }
#pragma unroll
    for (int o = 16; o; o >>= 1) s += __shfl_xor_sync(0xffffffffu, s, o);
    if (lane == 0) (which ? g_km : g_qm)[row] = (s != 0.f) ? 1.f : 0.f;
}

// ---------------------------------------------------------------------------
// Kernel 2: W transpose + convert.  g_Wt[z][n][k] = half(W_z[k][n]).
// ---------------------------------------------------------------------------
__global__ __launch_bounds__(256) void prep_w_kernel(const float* __restrict__ Wq,
                                                     const float* __restrict__ Wk,
                                                     const float* __restrict__ Wv) {
    const int z  = blockIdx.z;
    const float* W = (z == 0) ? Wq : (z == 1) ? Wk : Wv;
    const int k0 = blockIdx.x * 32;
    const int n0 = blockIdx.y * 32;
    __shared__ float ts[32][33];
    int e = threadIdx.x;
    {
        int kr = e >> 3, c4 = e & 7;
        float4 v = *(const float4*)(W + (size_t)(k0 + kr) * 512 + n0 + c4 * 4);
        ts[kr][c4 * 4 + 0] = v.x;
        ts[kr][c4 * 4 + 1] = v.y;
        ts[kr][c4 * 4 + 2] = v.z;
        ts[kr][c4 * 4 + 3] = v.w;
    }
    __syncthreads();
    {
        int n = e >> 3, g = e & 7;
        __half2 h0 = __floats2half2_rn(ts[g * 4 + 0][n], ts[g * 4 + 1][n]);
        __half2 h1 = __floats2half2_rn(ts[g * 4 + 2][n], ts[g * 4 + 3][n]);
        uint2 u = make_uint2(*(uint32_t*)&h0, *(uint32_t*)&h1);
        *(uint2*)(g_Wt + ((size_t)z * 512 + n0 + n) * 512 + k0 + g * 4) = u;
    }
}

// ---------------------------------------------------------------------------
// Kernel 3: projections, fp16 mma + ldmatrix + cp.async double buffer.
// CTA tile 128x128, K-step 32, 8 warps (4x2), warp tile 32x64.
// SMEM tiles: unpadded 64B rows with chunk-XOR swizzle (c ^= (row>>1)&3).
// ---------------------------------------------------------------------------
__global__ __launch_bounds__(256, 2) void proj_kernel() {
    const int z = blockIdx.z;
    const __half* A  = g_Ah + (size_t)(z ? 1 : 0) * 16384 * 512;
    const __half* Wt = g_Wt + (size_t)z * 512 * 512;

    const int m0 = blockIdx.y * 128;
    const int n0 = blockIdx.x * 128;

    __shared__ __align__(16) __half As[2 * 128 * 32];
    __shared__ __align__(16) __half Bs[2 * 128 * 32];
    const uint32_t aBase = (uint32_t)__cvta_generic_to_shared(As);
    const uint32_t bBase = (uint32_t)__cvta_generic_to_shared(Bs);

    const int tid  = threadIdx.x;
    const int lane = tid & 31;
    const int wid  = tid >> 5;
    const int wm   = wid & 3;
    const int wn   = wid >> 2;

    float acc[2][8][4];
#pragma unroll
    for (int i = 0; i < 2; i++)
#pragma unroll
        for (int j = 0; j < 8; j++)
#pragma unroll
            for (int r = 0; r < 4; r++) acc[i][j][r] = 0.f;

    // staging: 512 16B-chunks per tile, 2 per thread per tile
    const int srow = tid >> 2;          // 0..63  (two row-batches via +64)
    const int sc   = tid & 3;           // logical chunk
#define PROJ_ISSUE(k0, buf)                                                          \
    {                                                                                \
        _Pragma("unroll")                                                            \
        for (int r = 0; r < 2; r++) {                                                \
            int row  = srow + r * 64;                                                \
            int phys = sc ^ ((row >> 1) & 3);                                        \
            cp16(aBase + (buf) * 8192 + row * 64 + phys * 16,                        \
                 A + (size_t)(m0 + row) * 512 + (k0) + sc * 8);                      \
            cp16(bBase + (buf) * 8192 + row * 64 + phys * 16,                        \
                 Wt + (size_t)(n0 + row) * 512 + (k0) + sc * 8);                     \
        }                                                                            \
    }

    PROJ_ISSUE(0, 0);
    CP_COMMIT();

    for (int it = 0; it < 16; it++) {
        CP_WAIT0();
        __syncthreads();
        const int buf = it & 1;
        if (it + 1 < 16) {
            PROJ_ISSUE((it + 1) * 32, buf ^ 1);
            CP_COMMIT();
        }

        // A fragments: 4 ldmatrix.x4 (2 mi x 2 kg)
        uint32_t a[2][2][4];   // [kg][mi][]
#pragma unroll
        for (int kg = 0; kg < 2; kg++)
#pragma unroll
            for (int mi = 0; mi < 2; mi++) {
                int row  = wm * 32 + mi * 16 + (lane & 15);
                int c    = kg * 2 + (lane >> 4);
                int phys = c ^ ((row >> 1) & 3);
                ldsm4(a[kg][mi][0], a[kg][mi][1], a[kg][mi][2], a[kg][mi][3],
                      aBase + buf * 8192 + row * 64 + phys * 16);
            }
#pragma unroll
        for (int ni = 0; ni < 8; ni++) {
            int row  = wn * 64 + ni * 8 + (lane & 7);
            int c    = lane >> 3;
            int phys = c ^ ((row >> 1) & 3);
            uint32_t b0, b1, b2, b3;
            ldsm4(b0, b1, b2, b3, bBase + buf * 8192 + row * 64 + phys * 16);
            mma_f16(acc[0][ni], a[0][0][0], a[0][0][1], a[0][0][2], a[0][0][3], b0, b1);
            mma_f16(acc[1][ni], a[0][1][0], a[0][1][1], a[0][1][2], a[0][1][3], b0, b1);
            mma_f16(acc[0][ni], a[1][0][0], a[1][0][1], a[1][0][2], a[1][0][3], b2, b3);
            mma_f16(acc[1][ni], a[1][1][0], a[1][1][1], a[1][1][2], a[1][1][3], b2, b3);
        }
    }
#undef PROJ_ISSUE

    // epilogue
    const int gid = lane >> 2;
    const int tig = lane & 3;
#pragma unroll
    for (int mi = 0; mi < 2; mi++) {
#pragma unroll
        for (int ni = 0; ni < 8; ni++) {
            int gm = m0 + wm * 32 + mi * 16 + gid;
            int gn = n0 + wn * 64 + ni * 8 + tig * 2;
            int h = gn >> 6, d = gn & 63;
#pragma unroll
            for (int rr = 0; rr < 2; rr++) {
                int row = gm + rr * 8;
                int bb = row >> 9, ll = row & 511;
                float c0 = acc[mi][ni][rr * 2 + 0];
                float c1 = acc[mi][ni][rr * 2 + 1];
                int hb = h * 32 + bb;
                if (z == 2) {
                    size_t base = ((size_t)hb * 64 + d) * 512 + ll;
                    g_Vt[base]       = __float2half_rn(c0);
                    g_Vt[base + 512] = __float2half_rn(c1);
                } else {
                    __half2 hv = __floats2half2_rn(c0, c1);
                    __half* dst = (z == 0) ? g_Qh : g_Kh;
                    *(__half2*)(dst + ((size_t)hb * 512 + ll) * 64 + d) = hv;
                }
            }
        }
    }
}

// ---------------------------------------------------------------------------
// Kernel 4: fused flash attention, ldmatrix + cp.async KV prefetch.
// DYNAMIC shared memory (55296 B > 48KB static limit):
//   Qs: 128*72 halfs (18432 B), then KV: 2 stages x {K,V} x 64*72 halfs.
// Grid (4 q-tiles, 256 hb). 8 warps, warp owns 16 q-rows. Br=128, Bc=64.
// ---------------------------------------------------------------------------
#define ATTN_SMEM_BYTES (size_t)((128 * 72 + 2 * 2 * 64 * 72) * 2)   // 55296

__global__ __launch_bounds__(256, 2) void attn_kernel(const float* __restrict__ query,
                                                      float* __restrict__ out) {
    const int hb = blockIdx.y;
    const int h  = hb >> 5;
    const int b  = hb & 31;
    const int m0 = blockIdx.x * 128;

    const __half* Qh = g_Qh + (size_t)hb * L_ * DH;
    const __half* Kh = g_Kh + (size_t)hb * L_ * DH;
    const __half* Vt = g_Vt + (size_t)hb * DH * L_;

    extern __shared__ __align__(16) __half dynsm[];
    __half* Qs = dynsm;                   // [128][72]
    __half* KV = dynsm + 128 * 72;        // [stage][K|V][64][72]
    const uint32_t qBase  = (uint32_t)__cvta_generic_to_shared(Qs);
    const uint32_t kvBase = (uint32_t)__cvta_generic_to_shared(KV);
    const int KV_STAGE = 2 * 64 * 72 * 2;   // bytes per stage
    const int KV_VOFF  = 64 * 72 * 2;       // V offset within stage

    const int tid  = threadIdx.x;
    const int lane = tid & 31;
    const int wid  = tid >> 5;
    const int gid  = lane >> 2;
    const int tig  = lane & 3;
    const int q0   = m0 + wid * 16 + gid;
    const int q1   = q0 + 8;

    const int srow = tid >> 3;    // 0..31 (row batches via +32)
    const int sc   = tid & 7;     // chunk 0..7

    // ---- stage Q (group 0) ----
#pragma unroll
    for (int r = 0; r < 4; r++) {
        int row = srow + r * 32;
        cp16(qBase + row * 144 + sc * 16, Qh + (size_t)(m0 + row) * 64 + sc * 8);
    }
    CP_COMMIT();

#define ATTN_ISSUE_KV(k0, st)                                                        \
    {                                                                                \
        _Pragma("unroll")                                                            \
        for (int r = 0; r < 2; r++) {                                                \
            int kc = srow + r * 32;                                                  \
            cp16(kvBase + (st) * KV_STAGE + kc * 144 + sc * 16,                      \
                 Kh + (size_t)((k0) + kc) * 64 + sc * 8);                            \
            cp16(kvBase + (st) * KV_STAGE + KV_VOFF + kc * 144 + sc * 16,            \
                 Vt + (size_t)kc * 512 + (k0) + sc * 8);                             \
        }                                                                            \
    }

    ATTN_ISSUE_KV(0, 0);   // group 1
    CP_COMMIT();

    CP_WAIT1();            // Q ready (KV stage 0 may still be in flight)
    __syncthreads();

    // ---- Q fragments (held all kernel): 4 ldmatrix.x4 ----
    uint32_t Qa[4][4];
    {
        int row = wid * 16 + (lane & 15);
#pragma unroll
        for (int kg = 0; kg < 4; kg++) {
            int chunk = kg * 2 + (lane >> 4);
            ldsm4(Qa[kg][0], Qa[kg][1], Qa[kg][2], Qa[kg][3],
                  qBase + row * 144 + chunk * 16);
        }
    }

    float o[8][4];
#pragma unroll
    for (int di = 0; di < 8; di++)
#pragma unroll
        for (int j = 0; j < 4; j++) o[di][j] = 0.f;
    float mrun0 = -3.4e38f, mrun1 = -3.4e38f;
    float lrun0 = 0.f, lrun1 = 0.f;

    const int nkt = (m0 >> 6) + 2;
    for (int kt = 0; kt < nkt; kt++) {
        const int k0 = kt * 64;
        const int st = kt & 1;
        CP_WAIT0();
        __syncthreads();
        if (kt + 1 < nkt) {
            ATTN_ISSUE_KV(k0 + 64, st ^ 1);
            CP_COMMIT();
        }

        // ---- S = Q @ K^T : 16 ldmatrix.x4 + 32 mma ----
        const uint32_t kB = kvBase + st * KV_STAGE;
        float s[8][4];
#pragma unroll
        for (int ni = 0; ni < 8; ni++)
#pragma unroll
            for (int j = 0; j < 4; j++) s[ni][j] = 0.f;
#pragma unroll
        for (int ni = 0; ni < 8; ni++) {
            uint32_t addr = kB + (ni * 8 + (lane & 7)) * 144 + (lane >> 3) * 16;
            uint32_t b0, b1, b2, b3, c0, c1, c2, c3;
            ldsm4(b0, b1, b2, b3, addr);
            ldsm4(c0, c1, c2, c3, addr + 64);
            mma_f16(s[ni], Qa[0][0], Qa[0][1], Qa[0][2], Qa[0][3], b0, b1);
            mma_f16(s[ni], Qa[1][0], Qa[1][1], Qa[1][2], Qa[1][3], b2, b3);
            mma_f16(s[ni], Qa[2][0], Qa[2][1], Qa[2][2], Qa[2][3], c0, c1);
            mma_f16(s[ni], Qa[3][0], Qa[3][1], Qa[3][2], Qa[3][3], c2, c3);
        }

        // ---- scale + causal + key-mask ----
#pragma unroll
        for (int ni = 0; ni < 8; ni++) {
            int c0i = k0 + ni * 8 + tig * 2;
            float km0 = g_km[b * 512 + c0i];
            float km1 = g_km[b * 512 + c0i + 1];
            s[ni][0] = (c0i > q0     || km0 == 0.f) ? NEGV : s[ni][0] * 0.125f;
            s[ni][1] = (c0i + 1 > q0 || km1 == 0.f) ? NEGV : s[ni][1] * 0.125f;
            s[ni][2] = (c0i > q1     || km0 == 0.f) ? NEGV : s[ni][2] * 0.125f;
            s[ni][3] = (c0i + 1 > q1 || km1 == 0.f) ? NEGV : s[ni][3] * 0.125f;
        }

        // ---- online softmax ----
        float mx0 = -3.4e38f, mx1 = -3.4e38f;
#pragma unroll
        for (int ni = 0; ni < 8; ni++) {
            mx0 = fmaxf(mx0, fmaxf(s[ni][0], s[ni][1]));
            mx1 = fmaxf(mx1, fmaxf(s[ni][2], s[ni][3]));
        }
        mx0 = fmaxf(mx0, __shfl_xor_sync(0xffffffffu, mx0, 1));
        mx0 = fmaxf(mx0, __shfl_xor_sync(0xffffffffu, mx0, 2));
        mx1 = fmaxf(mx1, __shfl_xor_sync(0xffffffffu, mx1, 1));
        mx1 = fmaxf(mx1, __shfl_xor_sync(0xffffffffu, mx1, 2));

        float mn0 = fmaxf(mrun0, mx0), mn1 = fmaxf(mrun1, mx1);
        float al0 = __expf(mrun0 - mn0), al1 = __expf(mrun1 - mn1);
        mrun0 = mn0; mrun1 = mn1;

        float rs0 = 0.f, rs1 = 0.f;
#pragma unroll
        for (int ni = 0; ni < 8; ni++) {
            s[ni][0] = __expf(s[ni][0] - mn0);
            s[ni][1] = __expf(s[ni][1] - mn0);
            s[ni][2] = __expf(s[ni][2] - mn1);
            s[ni][3] = __expf(s[ni][3] - mn1);
            rs0 += s[ni][0] + s[ni][1];
            rs1 += s[ni][2] + s[ni][3];
        }
        rs0 += __shfl_xor_sync(0xffffffffu, rs0, 1);
        rs0 += __shfl_xor_sync(0xffffffffu, rs0, 2);
        rs1 += __shfl_xor_sync(0xffffffffu, rs1, 1);
        rs1 += __shfl_xor_sync(0xffffffffu, rs1, 2);
        lrun0 = lrun0 * al0 + rs0;
        lrun1 = lrun1 * al1 + rs1;
#pragma unroll
        for (int di = 0; di < 8; di++) {
            o[di][0] *= al0; o[di][1] *= al0;
            o[di][2] *= al1; o[di][3] *= al1;
        }

        // ---- P fragments (C-layout == A-layout) ----
        uint32_t Pa[4][4];
#pragma unroll
        for (int kg = 0; kg < 4; kg++) {
            Pa[kg][0] = h2u(s[2 * kg][0],     s[2 * kg][1]);
            Pa[kg][1] = h2u(s[2 * kg][2],     s[2 * kg][3]);
            Pa[kg][2] = h2u(s[2 * kg + 1][0], s[2 * kg + 1][1]);
            Pa[kg][3] = h2u(s[2 * kg + 1][2], s[2 * kg + 1][3]);
        }

        // ---- O += P @ V : 16 ldmatrix.x4 + 32 mma ----
        const uint32_t vB = kB + KV_VOFF;
#pragma unroll
        for (int di = 0; di < 8; di++) {
            uint32_t addr = vB + (di * 8 + (lane & 7)) * 144 + (lane >> 3) * 16;
            uint32_t b0, b1, b2, b3, c0, c1, c2, c3;
            ldsm4(b0, b1, b2, b3, addr);
            ldsm4(c0, c1, c2, c3, addr + 64);
            mma_f16(o[di], Pa[0][0], Pa[0][1], Pa[0][2], Pa[0][3], b0, b1);
            mma_f16(o[di], Pa[1][0], Pa[1][1], Pa[1][2], Pa[1][3], b2, b3);
            mma_f16(o[di], Pa[2][0], Pa[2][1], Pa[2][2], Pa[2][3], c0, c1);
            mma_f16(o[di], Pa[3][0], Pa[3][1], Pa[3][2], Pa[3][3], c2, c3);
        }
    }
#undef ATTN_ISSUE_KV

    // ---- epilogue: normalize, qmask, +query, merged-head store ----
    float sc0 = g_qm[b * 512 + q0] / lrun0;
    float sc1 = g_qm[b * 512 + q1] / lrun1;
#pragma unroll
    for (int di = 0; di < 8; di++) {
        int col = h * 64 + di * 8 + tig * 2;
        size_t i0 = ((size_t)(b * 512 + q0)) * 512 + col;
        size_t i1 = ((size_t)(b * 512 + q1)) * 512 + col;
        float2 qv0 = *(const float2*)(query + i0);
        float2 qv1 = *(const float2*)(query + i1);
        float2 w0, w1;
        w0.x = o[di][0] * sc0 + qv0.x;
        w0.y = o[di][1] * sc0 + qv0.y;
        w1.x = o[di][2] * sc1 + qv1.x;
        w1.y = o[di][3] * sc1 + qv1.y;
        *(float2*)(out + i0) = w0;
        *(float2*)(out + i1) = w1;
    }
}

// ---------------------------------------------------------------------------
// Launch
// ---------------------------------------------------------------------------
extern "C" void kernel_launch(void* const* d_in, const int* in_sizes, int n_in,
                              void* d_out, int out_size) {
    const float* query = (const float*)d_in[0];
    const float* key   = (const float*)d_in[1];
    const float* Wq    = (const float*)d_in[2];
    const float* Wk    = (const float*)d_in[3];
    const float* Wv    = (const float*)d_in[4];
    float* out = (float*)d_out;

    // Immediate (non-stream) API: capture-safe, idempotent, no allocation.
    cudaFuncSetAttribute(attn_kernel, cudaFuncAttributeMaxDynamicSharedMemorySize,
                         (int)ATTN_SMEM_BYTES);

    prep_qk_kernel<<<4096, 256>>>(query, key);
    prep_w_kernel<<<dim3(16, 16, 3), 256>>>(Wq, Wk, Wv);
    proj_kernel<<<dim3(4, 128, 3), 256>>>();
    attn_kernel<<<dim3(4, HB), 256, ATTN_SMEM_BYTES>>>(query, out);
}